// round 5
// baseline (speedup 1.0000x reference)
#include <cuda_runtime.h>
#include <cuda_bf16.h>

// DifferentiableSelector: y = sigmoid(scores/temp); y *= min(K/sum(y),1);
// 4x sequential refractory damping with circular shift; y[:,0]=0.
// One CTA per row, full row resident in dynamic smem (128 KB).

static constexpr int   T_DIM = 32768;
static constexpr int   NT    = 1024;   // threads per block
static constexpr int   E     = T_DIM / NT;  // 32 elements per thread
static constexpr float K_SEL = 64.0f;

__global__ __launch_bounds__(NT, 1)
void selector_kernel(const float* __restrict__ scores,
                     const float* __restrict__ log_temp,
                     float* __restrict__ out)
{
    extern __shared__ float y[];            // T_DIM floats
    __shared__ float red[32];
    __shared__ float s_scale;

    const int tid = threadIdx.x;
    const int row = blockIdx.x;
    const float* src = scores + (size_t)row * T_DIM;
    float*       dst = out    + (size_t)row * T_DIM;

    // temperature (scalar input, broadcast)
    float temp = __expf(log_temp[0]);
    temp = fminf(fmaxf(temp, 0.1f), 10.0f);
    const float invt = __fdividef(1.0f, temp);

    // ---- Phase 1: global load (float4) -> sigmoid -> smem, local sum ----
    float lsum = 0.0f;
    const float4* src4 = reinterpret_cast<const float4*>(src);
    float4*       y4   = reinterpret_cast<float4*>(y);
#pragma unroll
    for (int k = 0; k < E / 4; ++k) {
        const int idx = tid + k * NT;          // coalesced float4 index
        float4 v = src4[idx];
        float4 s;
        s.x = __fdividef(1.0f, 1.0f + __expf(-v.x * invt));
        s.y = __fdividef(1.0f, 1.0f + __expf(-v.y * invt));
        s.z = __fdividef(1.0f, 1.0f + __expf(-v.z * invt));
        s.w = __fdividef(1.0f, 1.0f + __expf(-v.w * invt));
        lsum += (s.x + s.y) + (s.z + s.w);
        y4[idx] = s;
    }

    // ---- Phase 2: block reduce -> budget scale ----
#pragma unroll
    for (int o = 16; o > 0; o >>= 1)
        lsum += __shfl_xor_sync(0xffffffffu, lsum, o);
    if ((tid & 31) == 0) red[tid >> 5] = lsum;
    __syncthreads();
    if (tid < 32) {
        float v = red[tid];
#pragma unroll
        for (int o = 16; o > 0; o >>= 1)
            v += __shfl_xor_sync(0xffffffffu, v, o);
        if (tid == 0) {
            const float budget = fmaxf(v, 1e-6f);
            s_scale = fminf(K_SEL / budget, 1.0f);
        }
    }
    __syncthreads();
    const float scale = s_scale;

    // ---- Phase 3: damping iterations. Interleaved ownership: thread t owns
    // elements {t + k*NT} -> conflict-free smem access across a warp.
    float a[E];

    // d = 1: fold the budget scale into both operands (saves one smem pass)
#pragma unroll
    for (int k = 0; k < E; ++k) {
        const int i = tid + k * NT;
        int j = i + 1; if (j >= T_DIM) j -= T_DIM;   // circular roll
        const float av = y[i] * scale;
        const float bv = y[j] * scale;
        const float f  = fminf(__fdividef(2.0f, 1.0f + av + bv), 1.0f);
        a[k] = av * f;
    }
    __syncthreads();
#pragma unroll
    for (int k = 0; k < E; ++k) y[tid + k * NT] = a[k];
    __syncthreads();

    // d = 2, 3: own value carried in registers, only neighbor read from smem
#pragma unroll
    for (int d = 2; d <= 3; ++d) {
#pragma unroll
        for (int k = 0; k < E; ++k) {
            const int i = tid + k * NT;
            int j = i + d; if (j >= T_DIM) j -= T_DIM;
            const float bv = y[j];
            const float f  = fminf(__fdividef(2.0f, 1.0f + a[k] + bv), 1.0f);
            a[k] *= f;
        }
        __syncthreads();
#pragma unroll
        for (int k = 0; k < E; ++k) y[tid + k * NT] = a[k];
        __syncthreads();
    }

    // d = 4: final iteration writes straight to GMEM (coalesced), zero col 0
#pragma unroll
    for (int k = 0; k < E; ++k) {
        const int i = tid + k * NT;
        int j = i + 4; if (j >= T_DIM) j -= T_DIM;
        const float bv = y[j];
        const float f  = fminf(__fdividef(2.0f, 1.0f + a[k] + bv), 1.0f);
        float v = a[k] * f;
        if (i == 0) v = 0.0f;
        dst[i] = v;
    }
}

extern "C" void kernel_launch(void* const* d_in, const int* in_sizes, int n_in,
                              void* d_out, int out_size)
{
    // metadata order: scores [B,T] fp32, log_temperature scalar fp32.
    // Pick by size defensively.
    const float* scores;
    const float* log_temp;
    int n_scores;
    if (in_sizes[0] > in_sizes[1]) {
        scores = (const float*)d_in[0]; log_temp = (const float*)d_in[1];
        n_scores = in_sizes[0];
    } else {
        scores = (const float*)d_in[1]; log_temp = (const float*)d_in[0];
        n_scores = in_sizes[1];
    }
    const int B = n_scores / T_DIM;          // 512
    const size_t smem = (size_t)T_DIM * sizeof(float);  // 128 KB

    static bool attr_set_ok = true;  // set every call; cheap, deterministic
    (void)attr_set_ok;
    cudaFuncSetAttribute(selector_kernel,
                         cudaFuncAttributeMaxDynamicSharedMemorySize,
                         (int)smem);

    float* outp = (float*)d_out;
    selector_kernel<<<B, NT, smem>>>(scores, log_temp, outp);
}

// round 6
// speedup vs baseline: 1.0251x; 1.0251x over previous
#include <cuda_runtime.h>
#include <cuda_bf16.h>

// DifferentiableSelector, 2-kernel tiled design:
//   K1: per-(row,segment) partial sums of sigmoid(scores/temp)  (budget pre-pass)
//   K2: per-tile sigmoid + budget scale + 4 refractory damping iters (halo=10,
//       recomputed locally -> zero cross-tile sync) + y[:,0]=0, write out.
// Damping factor min(2/(1+a+b),1) == 1.0 exactly when a+b<=1; a warp-uniform
// vote skips the division entirely on that (overwhelmingly common) path.

static constexpr int   T_DIM = 32768;
static constexpr int   SEGS  = 8;
static constexpr int   TILE  = T_DIM / SEGS;   // 4096
static constexpr int   HALO  = 10;             // dependency range of 4 iters: 1+2+3+4
static constexpr int   EXT   = TILE + HALO;    // 4106
static constexpr int   NT    = 512;
static constexpr int   EPT   = TILE / NT;      // 8 elements/thread (main body)
static constexpr float K_SEL = 64.0f;

// scratch: per-(row,seg) partial budget sums (max 1024 rows * 8 segs)
__device__ float g_partials[8192];

__device__ __forceinline__ float tanh_approx(float x) {
    float r; asm("tanh.approx.f32 %0, %1;" : "=f"(r) : "f"(x)); return r;
}

__device__ __forceinline__ float clipped_inv_temp(const float* log_temp) {
    float temp = __expf(log_temp[0]);
    temp = fminf(fmaxf(temp, 0.1f), 10.0f);
    return 1.0f / temp;
}

// ---------------- K1: budget partial sums ----------------
__global__ __launch_bounds__(NT)
void k1_partials(const float* __restrict__ scores,
                 const float* __restrict__ log_temp)
{
    __shared__ float red[NT / 32];
    const int bx  = blockIdx.x;
    const int row = bx >> 3;
    const int seg = bx & 7;
    const int tid = threadIdx.x;

    const float invt = clipped_inv_temp(log_temp);
    const float c    = 0.5f * invt;   // sigmoid(z) = 0.5*tanh(z/2) + 0.5

    const float4* src4 = reinterpret_cast<const float4*>(scores)
                       + (size_t)row * (T_DIM / 4) + seg * (TILE / 4);
    float lsum = 0.0f;
#pragma unroll
    for (int k = 0; k < TILE / 4 / NT; ++k) {          // 2 float4 loads/thread
        float4 v = src4[tid + k * NT];
        lsum += fmaf(0.5f, tanh_approx(v.x * c), 0.5f);
        lsum += fmaf(0.5f, tanh_approx(v.y * c), 0.5f);
        lsum += fmaf(0.5f, tanh_approx(v.z * c), 0.5f);
        lsum += fmaf(0.5f, tanh_approx(v.w * c), 0.5f);
    }
#pragma unroll
    for (int o = 16; o > 0; o >>= 1)
        lsum += __shfl_xor_sync(0xffffffffu, lsum, o);
    if ((tid & 31) == 0) red[tid >> 5] = lsum;
    __syncthreads();
    if (tid < 32) {
        float v = (tid < NT / 32) ? red[tid] : 0.0f;
#pragma unroll
        for (int o = 8; o > 0; o >>= 1)
            v += __shfl_xor_sync(0xffffffffu, v, o);
        if (tid == 0) g_partials[bx] = v;
    }
}

// ---------------- K2: sigmoid + scale + damping + store ----------------
__global__ __launch_bounds__(NT, 3)
void k2_damp(const float* __restrict__ scores,
             const float* __restrict__ log_temp,
             float* __restrict__ out)
{
    __shared__ float ys[EXT];
    __shared__ float s_scale;

    const int bx   = blockIdx.x;
    const int row  = bx >> 3;
    const int seg  = bx & 7;
    const int tid  = threadIdx.x;
    const int base = seg * TILE;
    const float* src = scores + (size_t)row * T_DIM;
    float*       dst = out    + (size_t)row * T_DIM + base;

    const float invt = clipped_inv_temp(log_temp);

    // budget -> scale (deterministic fixed-order sum of 8 partials)
    if (tid == 0) {
        float b = 0.0f;
#pragma unroll
        for (int j = 0; j < SEGS; ++j) b += g_partials[(row << 3) + j];
        b = fmaxf(b, 1e-6f);
        s_scale = fminf(K_SEL / b, 1.0f);
    }

    // Phase 1: sigmoid into smem (unscaled; scale folded into iter 1)
#pragma unroll
    for (int k = 0; k < EPT; ++k) {
        const int i = tid + k * NT;
        float x = src[base + i];
        ys[i] = __fdividef(1.0f, 1.0f + __expf(-x * invt));
    }
    if (tid < HALO) {
        int g = base + TILE + tid; if (g >= T_DIM) g -= T_DIM;   // circular roll
        float x = src[g];
        ys[TILE + tid] = __fdividef(1.0f, 1.0f + __expf(-x * invt));
    }
    __syncthreads();
    const float scale = s_scale;

    // ---- iter d=1 (scale folded into both operands), valid range [0, TILE+9)
    {
        float v[EPT];
#pragma unroll
        for (int k = 0; k < EPT; ++k) {
            const int i = tid + k * NT;
            const float a = ys[i] * scale;
            const float b = ys[i + 1] * scale;
            const float s = a + b;
            float nv = a;                       // f == 1 exactly when s <= 1
            if (__any_sync(0xffffffffu, s > 1.0f)) {
                if (s > 1.0f) nv = a * __fdividef(2.0f, 1.0f + s);
            }
            v[k] = nv;
        }
        float vt = 0.0f;
        if (tid < TILE + 9 - TILE) {            // tail i in [TILE, TILE+9)
            const int i = TILE + tid;
            const float a = ys[i] * scale;
            const float b = ys[i + 1] * scale;
            const float s = a + b;
            vt = (s > 1.0f) ? a * __fdividef(2.0f, 1.0f + s) : a;
        }
        __syncthreads();
#pragma unroll
        for (int k = 0; k < EPT; ++k) ys[tid + k * NT] = v[k];
        if (tid < 9) ys[TILE + tid] = vt;
        __syncthreads();
    }

    // ---- iters d=2,3: valid ranges [0, TILE+7), [0, TILE+4)
#pragma unroll
    for (int d = 2; d <= 3; ++d) {
        const int tail = (d == 2) ? 7 : 4;
        float v[EPT];
#pragma unroll
        for (int k = 0; k < EPT; ++k) {
            const int i = tid + k * NT;
            const float a = ys[i];
            const float b = ys[i + d];
            const float s = a + b;
            float nv = a;
            if (__any_sync(0xffffffffu, s > 1.0f)) {
                if (s > 1.0f) nv = a * __fdividef(2.0f, 1.0f + s);
            }
            v[k] = nv;
        }
        float vt = 0.0f;
        if (tid < tail) {
            const int i = TILE + tid;
            const float a = ys[i];
            const float b = ys[i + d];
            const float s = a + b;
            vt = (s > 1.0f) ? a * __fdividef(2.0f, 1.0f + s) : a;
        }
        __syncthreads();
#pragma unroll
        for (int k = 0; k < EPT; ++k) ys[tid + k * NT] = v[k];
        if (tid < tail) ys[TILE + tid] = vt;
        __syncthreads();
    }

    // ---- iter d=4: compute [0, TILE) and write straight to GMEM; zero col 0
#pragma unroll
    for (int k = 0; k < EPT; ++k) {
        const int i = tid + k * NT;
        const float a = ys[i];
        const float b = ys[i + 4];
        const float s = a + b;
        float nv = a;
        if (__any_sync(0xffffffffu, s > 1.0f)) {
            if (s > 1.0f) nv = a * __fdividef(2.0f, 1.0f + s);
        }
        if (base + i == 0) nv = 0.0f;
        dst[i] = nv;
    }
}

extern "C" void kernel_launch(void* const* d_in, const int* in_sizes, int n_in,
                              void* d_out, int out_size)
{
    // metadata order: scores [B,T] fp32, log_temperature scalar fp32 (pick by size)
    const float* scores;
    const float* log_temp;
    int n_scores;
    if (in_sizes[0] > in_sizes[1]) {
        scores = (const float*)d_in[0]; log_temp = (const float*)d_in[1];
        n_scores = in_sizes[0];
    } else {
        scores = (const float*)d_in[1]; log_temp = (const float*)d_in[0];
        n_scores = in_sizes[1];
    }
    const int B = n_scores / T_DIM;               // 512
    float* outp = (float*)d_out;

    k1_partials<<<B * SEGS, NT>>>(scores, log_temp);
    k2_damp    <<<B * SEGS, NT>>>(scores, log_temp, outp);
}

// round 7
// speedup vs baseline: 1.1115x; 1.0842x over previous
#include <cuda_runtime.h>
#include <cuda_bf16.h>

// DifferentiableSelector, 2-kernel design with identity-damping fast path:
//  K1: per-(row,quarter) partial sums of sigmoid(scores/temp)   (budget)
//  K2: sigmoid + scale; block proves 2*scale*max(tile+halo) <= 1 =>
//      min(2/(1+a+b),1) == 1 for ALL 4 damping iters (values only shrink),
//      so damping is the identity -> direct coalesced store.
//      Fallback (per-CTA): exact per-thread contiguous register recompute
//      (chunk 8 + halo 10) from initial sigmoids staged in padded smem.

static constexpr int   T_DIM = 32768;
static constexpr float K_SEL = 64.0f;

// K1 tiling
static constexpr int SEG1  = 4;
static constexpr int TILE1 = T_DIM / SEG1;   // 8192
static constexpr int NT1   = 512;
// K2 tiling
static constexpr int SEG2  = 8;
static constexpr int TILE2 = T_DIM / SEG2;   // 4096
static constexpr int NT2   = 512;
static constexpr int C     = TILE2 / NT2;    // 8 contiguous elems/thread (slow path)
static constexpr int HALO  = 10;             // 1+2+3+4 dependency radius
static constexpr int EXT   = TILE2 + HALO;   // 4106

// padded smem layout: +1 float every 8 -> slow-path reads (stride 9) conflict-free
__device__ __forceinline__ int PADI(int i) { return i + (i >> 3); }
static constexpr int SMEM_PAD = 4106 + (4105 >> 3) + 1;   // PADI(EXT-1)+1 = 4619

__device__ float g_partials[8192];   // row-major [row][SEG1]

__device__ __forceinline__ float tanh_approx(float x) {
    float r; asm("tanh.approx.f32 %0, %1;" : "=f"(r) : "f"(x)); return r;
}
__device__ __forceinline__ float clipped_inv_temp(const float* log_temp) {
    float temp = __expf(log_temp[0]);
    temp = fminf(fmaxf(temp, 0.1f), 10.0f);
    return 1.0f / temp;
}
__device__ __forceinline__ float sigmoidf(float x, float invt) {
    return __fdividef(1.0f, 1.0f + __expf(-x * invt));
}

// ---------------- K1: budget partial sums (DRAM-read bound) ----------------
__global__ __launch_bounds__(NT1)
void k1_partials(const float* __restrict__ scores,
                 const float* __restrict__ log_temp)
{
    __shared__ float red[NT1 / 32];
    const int bx  = blockIdx.x;
    const int row = bx >> 2;
    const int seg = bx & 3;
    const int tid = threadIdx.x;

    const float c = 0.5f * clipped_inv_temp(log_temp);  // sigmoid = 0.5*tanh(x/2)+0.5

    const float4* src4 = reinterpret_cast<const float4*>(scores)
                       + (size_t)row * (T_DIM / 4) + seg * (TILE1 / 4);
    float lsum = 0.0f;
#pragma unroll
    for (int k = 0; k < TILE1 / 4 / NT1; ++k) {        // 4 float4 loads/thread (MLP=4)
        float4 v = src4[tid + k * NT1];
        lsum += fmaf(0.5f, tanh_approx(v.x * c), 0.5f);
        lsum += fmaf(0.5f, tanh_approx(v.y * c), 0.5f);
        lsum += fmaf(0.5f, tanh_approx(v.z * c), 0.5f);
        lsum += fmaf(0.5f, tanh_approx(v.w * c), 0.5f);
    }
#pragma unroll
    for (int o = 16; o > 0; o >>= 1)
        lsum += __shfl_xor_sync(0xffffffffu, lsum, o);
    if ((tid & 31) == 0) red[tid >> 5] = lsum;
    __syncthreads();
    if (tid < 32) {
        float v = (tid < NT1 / 32) ? red[tid] : 0.0f;
#pragma unroll
        for (int o = 8; o > 0; o >>= 1)
            v += __shfl_xor_sync(0xffffffffu, v, o);
        if (tid == 0) g_partials[bx] = v;
    }
}

// ---------------- K2: sigmoid + scale (+ identity/exact damping) ----------------
__global__ __launch_bounds__(NT2, 3)
void k2_damp(const float* __restrict__ scores,
             const float* __restrict__ log_temp,
             float* __restrict__ out)
{
    __shared__ float ys[SMEM_PAD];       // used only on slow path
    __shared__ float red[NT2 / 32];
    __shared__ float s_scale, s_max;

    const int bx   = blockIdx.x;
    const int row  = bx >> 3;
    const int seg  = bx & 7;
    const int tid  = threadIdx.x;
    const int base = seg * TILE2;
    const float* src = scores + (size_t)row * T_DIM;
    float*       dst = out    + (size_t)row * T_DIM + base;

    const float invt = clipped_inv_temp(log_temp);

    // --- sigmoid of own (interleaved float4) elements, kept in registers ---
    const float4* src4 = reinterpret_cast<const float4*>(src) + (base >> 2);
    float4 s0, s1;
    {
        float4 v0 = src4[tid];
        float4 v1 = src4[tid + NT2];
        s0.x = sigmoidf(v0.x, invt); s0.y = sigmoidf(v0.y, invt);
        s0.z = sigmoidf(v0.z, invt); s0.w = sigmoidf(v0.w, invt);
        s1.x = sigmoidf(v1.x, invt); s1.y = sigmoidf(v1.y, invt);
        s1.z = sigmoidf(v1.z, invt); s1.w = sigmoidf(v1.w, invt);
    }
    // halo (wraps within the row per jnp.roll)
    float yh = 0.0f;
    if (tid < HALO) {
        int g = base + TILE2 + tid; if (g >= T_DIM) g -= T_DIM;
        yh = sigmoidf(src[g], invt);
    }

    // --- block max (incl. halo) + budget scale, two barriers total ---
    float m = fmaxf(fmaxf(fmaxf(s0.x, s0.y), fmaxf(s0.z, s0.w)),
                    fmaxf(fmaxf(s1.x, s1.y), fmaxf(s1.z, s1.w)));
    m = fmaxf(m, yh);
#pragma unroll
    for (int o = 16; o > 0; o >>= 1)
        m = fmaxf(m, __shfl_xor_sync(0xffffffffu, m, o));
    if ((tid & 31) == 0) red[tid >> 5] = m;
    __syncthreads();
    if (tid < 32) {
        float v = (tid < NT2 / 32) ? red[tid] : 0.0f;
#pragma unroll
        for (int o = 8; o > 0; o >>= 1)
            v = fmaxf(v, __shfl_xor_sync(0xffffffffu, v, o));
        if (tid == 0) {
            s_max = v;
            float b = 0.0f;
#pragma unroll
            for (int j = 0; j < SEG1; ++j) b += g_partials[(row << 2) + j];
            b = fmaxf(b, 1e-6f);
            s_scale = fminf(K_SEL / b, 1.0f);
        }
    }
    __syncthreads();
    const float scale = s_scale;

    if (2.0f * scale * s_max <= 1.0f) {
        // ---- FAST PATH: all damping factors are exactly 1 -> identity ----
        s0.x *= scale; s0.y *= scale; s0.z *= scale; s0.w *= scale;
        s1.x *= scale; s1.y *= scale; s1.z *= scale; s1.w *= scale;
        if (base == 0 && tid == 0) s0.x = 0.0f;   // y[:,0] = 0
        float4* dst4 = reinterpret_cast<float4*>(dst);
        dst4[tid]       = s0;
        dst4[tid + NT2] = s1;
        return;
    }

    // ---- SLOW PATH (exact, per-CTA): stage initial sigmoids, recompute ----
    {
        const int e0 = 4 * tid;          // own elements 4*(tid+k*NT2)+c
        ys[PADI(e0 + 0)] = s0.x; ys[PADI(e0 + 1)] = s0.y;
        ys[PADI(e0 + 2)] = s0.z; ys[PADI(e0 + 3)] = s0.w;
        const int e1 = 4 * (tid + NT2);
        ys[PADI(e1 + 0)] = s1.x; ys[PADI(e1 + 1)] = s1.y;
        ys[PADI(e1 + 2)] = s1.z; ys[PADI(e1 + 3)] = s1.w;
        if (tid < HALO) ys[PADI(TILE2 + tid)] = yh;
    }
    __syncthreads();

    float a[C + HALO];
    {
        const int s = C * tid;           // contiguous chunk + halo, stride-9 reads
#pragma unroll
        for (int j = 0; j < C + HALO; ++j) a[j] = ys[PADI(s + j)] * scale;
    }
    // in-place forward updates; valid ranges shrink by d each iteration
#pragma unroll
    for (int j = 0; j < 17; ++j) {
        const float s = a[j] + a[j + 1];
        a[j] *= fminf(__fdividef(2.0f, 1.0f + s), 1.0f);
    }
#pragma unroll
    for (int j = 0; j < 15; ++j) {
        const float s = a[j] + a[j + 2];
        a[j] *= fminf(__fdividef(2.0f, 1.0f + s), 1.0f);
    }
#pragma unroll
    for (int j = 0; j < 12; ++j) {
        const float s = a[j] + a[j + 3];
        a[j] *= fminf(__fdividef(2.0f, 1.0f + s), 1.0f);
    }
#pragma unroll
    for (int j = 0; j < 8; ++j) {
        const float s = a[j] + a[j + 4];
        a[j] *= fminf(__fdividef(2.0f, 1.0f + s), 1.0f);
    }
    if (base == 0 && tid == 0) a[0] = 0.0f;       // y[:,0] = 0
#pragma unroll
    for (int j = 0; j < C; ++j) dst[C * tid + j] = a[j];
}

extern "C" void kernel_launch(void* const* d_in, const int* in_sizes, int n_in,
                              void* d_out, int out_size)
{
    // metadata order: scores [B,T] fp32, log_temperature scalar fp32 (pick by size)
    const float* scores;
    const float* log_temp;
    int n_scores;
    if (in_sizes[0] > in_sizes[1]) {
        scores = (const float*)d_in[0]; log_temp = (const float*)d_in[1];
        n_scores = in_sizes[0];
    } else {
        scores = (const float*)d_in[1]; log_temp = (const float*)d_in[0];
        n_scores = in_sizes[1];
    }
    const int B = n_scores / T_DIM;               // 512
    float* outp = (float*)d_out;

    k1_partials<<<B * SEG1, NT1>>>(scores, log_temp);
    k2_damp    <<<B * SEG2, NT2>>>(scores, log_temp, outp);
}

// round 8
// speedup vs baseline: 1.6423x; 1.4776x over previous
#include <cuda_runtime.h>
#include <cuda_bf16.h>

// DifferentiableSelector, 3-kernel streaming design:
//  K1:      per-(row,quarter) partial sums of sigmoid(scores/temp) AND partial
//           max of raw scores (sigmoid monotone => max y = sigmoid(max x)).
//  Kscale:  512 threads combine partials -> per-row scale; sign encodes the
//           identity-damping proof (2*scale*ymax <= 1 => every damping factor
//           min(2/(1+a+b),1) == 1 exactly, and damping only shrinks values).
//  K2:      pure-streaming: load -> sigmoid -> *scale -> store. No barriers,
//           no reductions, no smem on the fast path. Exact per-CTA slow-path
//           fallback (contiguous chunk + halo register recompute).

static constexpr int   T_DIM = 32768;
static constexpr float K_SEL = 64.0f;

// K1 tiling
static constexpr int SEG1  = 4;
static constexpr int TILE1 = T_DIM / SEG1;   // 8192
static constexpr int NT1   = 256;            // 8 float4 loads/thread (MLP 8)
// K2 tiling
static constexpr int SEG2  = 8;
static constexpr int TILE2 = T_DIM / SEG2;   // 4096
static constexpr int NT2   = 256;            // 4 float4 loads/thread (MLP 4)
static constexpr int C     = TILE2 / NT2;    // 16 contiguous elems/thread (slow path)
static constexpr int HALO  = 10;             // 1+2+3+4 dependency radius
static constexpr int EXT   = TILE2 + HALO;   // 4106

// padded smem (slow path only): +1 float every 8
__device__ __forceinline__ int PADI(int i) { return i + (i >> 3); }
static constexpr int SMEM_PAD = EXT + ((EXT - 1) >> 3) + 1;   // 4620

__device__ float g_partials[4096];   // [row][SEG1] sums
__device__ float g_pmax[4096];       // [row][SEG1] raw-score maxes
__device__ float g_scale[1024];      // per-row: +scale (fast) / -scale (slow)

__device__ __forceinline__ float tanh_approx(float x) {
    float r; asm("tanh.approx.f32 %0, %1;" : "=f"(r) : "f"(x)); return r;
}
__device__ __forceinline__ float clipped_inv_temp(const float* log_temp) {
    float temp = __expf(log_temp[0]);
    temp = fminf(fmaxf(temp, 0.1f), 10.0f);
    return 1.0f / temp;
}
__device__ __forceinline__ float sigmoidf(float x, float invt) {
    return __fdividef(1.0f, 1.0f + __expf(-x * invt));
}

// ---------------- K1: budget partial sums + raw max ----------------
__global__ __launch_bounds__(NT1)
void k1_partials(const float* __restrict__ scores,
                 const float* __restrict__ log_temp)
{
    __shared__ float reds[NT1 / 32];
    __shared__ float redm[NT1 / 32];
    const int bx  = blockIdx.x;
    const int row = bx >> 2;
    const int seg = bx & 3;
    const int tid = threadIdx.x;

    const float c = 0.5f * clipped_inv_temp(log_temp);  // sigmoid = 0.5*tanh(x/2)+0.5

    const float4* src4 = reinterpret_cast<const float4*>(scores)
                       + (size_t)row * (T_DIM / 4) + seg * (TILE1 / 4);
    float4 v[TILE1 / 4 / NT1];                          // 8 outstanding float4 loads
#pragma unroll
    for (int k = 0; k < TILE1 / 4 / NT1; ++k) v[k] = src4[tid + k * NT1];

    float lsum = 0.0f;
    float lmax = -3.4e38f;
#pragma unroll
    for (int k = 0; k < TILE1 / 4 / NT1; ++k) {
        lsum += fmaf(0.5f, tanh_approx(v[k].x * c), 0.5f);
        lsum += fmaf(0.5f, tanh_approx(v[k].y * c), 0.5f);
        lsum += fmaf(0.5f, tanh_approx(v[k].z * c), 0.5f);
        lsum += fmaf(0.5f, tanh_approx(v[k].w * c), 0.5f);
        lmax = fmaxf(lmax, fmaxf(fmaxf(v[k].x, v[k].y), fmaxf(v[k].z, v[k].w)));
    }
#pragma unroll
    for (int o = 16; o > 0; o >>= 1) {
        lsum += __shfl_xor_sync(0xffffffffu, lsum, o);
        lmax = fmaxf(lmax, __shfl_xor_sync(0xffffffffu, lmax, o));
    }
    if ((tid & 31) == 0) { reds[tid >> 5] = lsum; redm[tid >> 5] = lmax; }
    __syncthreads();
    if (tid < 32) {
        float s = (tid < NT1 / 32) ? reds[tid] : 0.0f;
        float m = (tid < NT1 / 32) ? redm[tid] : -3.4e38f;
#pragma unroll
        for (int o = 4; o > 0; o >>= 1) {
            s += __shfl_xor_sync(0xffffffffu, s, o);
            m = fmaxf(m, __shfl_xor_sync(0xffffffffu, m, o));
        }
        if (tid == 0) { g_partials[bx] = s; g_pmax[bx] = m; }
    }
}

// ---------------- Kscale: per-row scale + fast/slow flag (sign) ----------------
__global__ void k_scale(const float* __restrict__ log_temp, int B)
{
    const int r = blockIdx.x * blockDim.x + threadIdx.x;
    if (r >= B) return;
    const float invt = clipped_inv_temp(log_temp);
    float b = 0.0f, mx = -3.4e38f;
#pragma unroll
    for (int j = 0; j < SEG1; ++j) {
        b += g_partials[(r << 2) + j];
        mx = fmaxf(mx, g_pmax[(r << 2) + j]);
    }
    b = fmaxf(b, 1e-6f);
    const float scale = fminf(K_SEL / b, 1.0f);
    const float ymax  = sigmoidf(mx, invt);     // same formula as K2 -> exact bound
    const bool  fast  = (2.0f * scale * ymax <= 1.0f);
    g_scale[r] = fast ? scale : -scale;
}

// ---------------- K2: streaming sigmoid*scale (+ exact slow fallback) ----------------
__global__ __launch_bounds__(NT2, 8)
void k2_damp(const float* __restrict__ scores,
             const float* __restrict__ log_temp,
             float* __restrict__ out)
{
    __shared__ float ys[SMEM_PAD];       // slow path only
    const int bx   = blockIdx.x;
    const int row  = bx >> 3;
    const int seg  = bx & 7;
    const int tid  = threadIdx.x;
    const int base = seg * TILE2;
    const float* src = scores + (size_t)row * T_DIM;
    float*       dst = out    + (size_t)row * T_DIM + base;

    // issue all loads first (MLP 4), uniform scalar alongside
    const float4* src4 = reinterpret_cast<const float4*>(src) + (base >> 2);
    float4 v[4];
#pragma unroll
    for (int k = 0; k < 4; ++k) v[k] = src4[tid + k * NT2];
    const float sc    = g_scale[row];
    const float invt  = clipped_inv_temp(log_temp);
    const float scale = fabsf(sc);

    float4 s[4];
#pragma unroll
    for (int k = 0; k < 4; ++k) {
        s[k].x = sigmoidf(v[k].x, invt);
        s[k].y = sigmoidf(v[k].y, invt);
        s[k].z = sigmoidf(v[k].z, invt);
        s[k].w = sigmoidf(v[k].w, invt);
    }

    if (sc >= 0.0f) {
        // ---- FAST PATH: damping is the identity; pure elementwise store ----
        float4* dst4 = reinterpret_cast<float4*>(dst);
#pragma unroll
        for (int k = 0; k < 4; ++k) {
            s[k].x *= scale; s[k].y *= scale; s[k].z *= scale; s[k].w *= scale;
        }
        if (base == 0 && tid == 0) s[0].x = 0.0f;   // y[:,0] = 0
#pragma unroll
        for (int k = 0; k < 4; ++k) dst4[tid + k * NT2] = s[k];
        return;
    }

    // ---- SLOW PATH (exact): stage sigmoids, per-thread contiguous recompute ----
#pragma unroll
    for (int k = 0; k < 4; ++k) {
        const int e = 4 * (tid + k * NT2);
        ys[PADI(e + 0)] = s[k].x; ys[PADI(e + 1)] = s[k].y;
        ys[PADI(e + 2)] = s[k].z; ys[PADI(e + 3)] = s[k].w;
    }
    if (tid < HALO) {
        int g = base + TILE2 + tid; if (g >= T_DIM) g -= T_DIM;  // circular roll
        ys[PADI(TILE2 + tid)] = sigmoidf(src[g], invt);
    }
    __syncthreads();

    float a[C + HALO];
    {
        const int st = C * tid;
#pragma unroll
        for (int j = 0; j < C + HALO; ++j) a[j] = ys[PADI(st + j)] * scale;
    }
#pragma unroll
    for (int j = 0; j < C + 9; ++j) {            // d=1
        const float t = a[j] + a[j + 1];
        a[j] *= fminf(__fdividef(2.0f, 1.0f + t), 1.0f);
    }
#pragma unroll
    for (int j = 0; j < C + 7; ++j) {            // d=2
        const float t = a[j] + a[j + 2];
        a[j] *= fminf(__fdividef(2.0f, 1.0f + t), 1.0f);
    }
#pragma unroll
    for (int j = 0; j < C + 4; ++j) {            // d=3
        const float t = a[j] + a[j + 3];
        a[j] *= fminf(__fdividef(2.0f, 1.0f + t), 1.0f);
    }
#pragma unroll
    for (int j = 0; j < C; ++j) {                // d=4
        const float t = a[j] + a[j + 4];
        a[j] *= fminf(__fdividef(2.0f, 1.0f + t), 1.0f);
    }
    if (base == 0 && tid == 0) a[0] = 0.0f;      // y[:,0] = 0
#pragma unroll
    for (int j = 0; j < C; ++j) dst[C * tid + j] = a[j];
}

extern "C" void kernel_launch(void* const* d_in, const int* in_sizes, int n_in,
                              void* d_out, int out_size)
{
    // metadata order: scores [B,T] fp32, log_temperature scalar fp32 (pick by size)
    const float* scores;
    const float* log_temp;
    int n_scores;
    if (in_sizes[0] > in_sizes[1]) {
        scores = (const float*)d_in[0]; log_temp = (const float*)d_in[1];
        n_scores = in_sizes[0];
    } else {
        scores = (const float*)d_in[1]; log_temp = (const float*)d_in[0];
        n_scores = in_sizes[1];
    }
    const int B = n_scores / T_DIM;               // 512
    float* outp = (float*)d_out;

    k1_partials<<<B * SEG1, NT1>>>(scores, log_temp);
    k_scale    <<<(B + 255) / 256, 256>>>(log_temp, B);
    k2_damp    <<<B * SEG2, NT2>>>(scores, log_temp, outp);
}

// round 9
// speedup vs baseline: 1.7260x; 1.0510x over previous
#include <cuda_runtime.h>
#include <cuda_bf16.h>

// DifferentiableSelector, fully fused single kernel: one CTA per row.
//  - 32 elements/thread in registers (8 x float4), scores read exactly ONCE.
//  - sigmoid = ex2.approx (1 MUFU) + Newton reciprocal on the FMA pipe:
//      e = 2^(-|z|*log2e) in (0,1], d = 1+e in (1,2],
//      r ~= 1/d via linear minimax seed + 3 Newton steps (rel err ~3e-9),
//      sigmoid(z) = z>=0 ? r : e*r.
//  - block reduce sum (budget) + max; 2*scale*ymax <= 1 proves every damping
//    factor min(2/(1+a+b),1) == 1 exactly (damping only shrinks values) ->
//    fast path stores y*scale straight from registers.
//  - exact slow path (arbitrary inputs): chunked smem staging (8192+halo) and
//    per-thread forward recompute of the 4 damping iterations.

static constexpr int   T_DIM = 32768;
static constexpr int   NT    = 1024;
static constexpr int   VPT   = T_DIM / NT / 4;   // 8 float4 per thread
static constexpr float K_SEL = 64.0f;

// slow-path chunking: 4 chunks of 8192 elements, halo 10 (use 12 = 3 float4)
static constexpr int CHUNK = 8192;
static constexpr int CPT   = CHUNK / NT;         // 8 contiguous elems/thread

__device__ __forceinline__ float ex2_approx(float x) {
    float r; asm("ex2.approx.ftz.f32 %0, %1;" : "=f"(r) : "f"(x)); return r;
}

// sigmoid(z') where z' = x * invt, via 1 MUFU + FMA-pipe Newton reciprocal.
// c2 = invt * log2(e). Updates sum and max.
__device__ __forceinline__ float sig1(float x, float c2, float& sum, float& mx) {
    const float e = ex2_approx(-fabsf(x) * c2);     // e in (0, 1]
    const float d = 1.0f + e;                       // d in (1, 2]
    float r = fmaf(-0.5f, d, 1.45710678f);          // minimax seed, rel err 8.6e-2
    float t = fmaf(d, r, -2.0f); r = -r * t;        // Newton 1: 7.4e-3
    t = fmaf(d, r, -2.0f); r = -r * t;              // Newton 2: 5.4e-5
    t = fmaf(d, r, -2.0f); r = -r * t;              // Newton 3: 2.9e-9
    const float s = (x >= 0.0f) ? r : e * r;        // sigmoid
    sum += s;
    mx = fmaxf(mx, s);
    return s;
}

__global__ __launch_bounds__(NT, 1)
void fused_selector(const float* __restrict__ scores,
                    const float* __restrict__ log_temp,
                    float* __restrict__ out)
{
    __shared__ float ys[CHUNK + 12];     // slow path staging
    __shared__ float reds[32], redm[32];
    __shared__ float s_scale;
    __shared__ int   s_fast;

    const int tid = threadIdx.x;
    const int row = blockIdx.x;
    const float4* src4 = reinterpret_cast<const float4*>(scores) + (size_t)row * (T_DIM / 4);
    float4*       dst4 = reinterpret_cast<float4*>(out)          + (size_t)row * (T_DIM / 4);

    float temp = __expf(log_temp[0]);
    temp = fminf(fmaxf(temp, 0.1f), 10.0f);
    const float c2 = __fdividef(1.442695040888963f, temp);   // log2(e)/temp

    // ---- single read of the row: 8 outstanding float4 streaming loads ----
    float4 v[VPT];
#pragma unroll
    for (int k = 0; k < VPT; ++k) v[k] = __ldcs(src4 + tid + k * NT);

    // ---- sigmoid in place + per-thread sum/max ----
    float sum = 0.0f, mx = 0.0f;
#pragma unroll
    for (int k = 0; k < VPT; ++k) {
        v[k].x = sig1(v[k].x, c2, sum, mx);
        v[k].y = sig1(v[k].y, c2, sum, mx);
        v[k].z = sig1(v[k].z, c2, sum, mx);
        v[k].w = sig1(v[k].w, c2, sum, mx);
    }

    // ---- block reduction: sum (budget) and max (identity-damping proof) ----
#pragma unroll
    for (int o = 16; o > 0; o >>= 1) {
        sum += __shfl_xor_sync(0xffffffffu, sum, o);
        mx = fmaxf(mx, __shfl_xor_sync(0xffffffffu, mx, o));
    }
    if ((tid & 31) == 0) { reds[tid >> 5] = sum; redm[tid >> 5] = mx; }
    __syncthreads();
    if (tid < 32) {
        float s = reds[tid];
        float m = redm[tid];
#pragma unroll
        for (int o = 16; o > 0; o >>= 1) {
            s += __shfl_xor_sync(0xffffffffu, s, o);
            m = fmaxf(m, __shfl_xor_sync(0xffffffffu, m, o));
        }
        if (tid == 0) {
            const float b     = fmaxf(s, 1e-6f);
            const float scale = fminf(K_SEL / b, 1.0f);
            s_scale = scale;
            s_fast  = (2.0f * scale * m <= 1.0f) ? 1 : 0;
        }
    }
    __syncthreads();
    const float scale = s_scale;

    if (s_fast) {
        // ---- FAST PATH: damping is the identity -> scale and store ----
#pragma unroll
        for (int k = 0; k < VPT; ++k) {
            v[k].x *= scale; v[k].y *= scale; v[k].z *= scale; v[k].w *= scale;
        }
        if (tid == 0) v[0].x = 0.0f;                 // y[:,0] = 0
#pragma unroll
        for (int k = 0; k < VPT; ++k) __stcs(dst4 + tid + k * NT, v[k]);
        return;
    }

    // ---- SLOW PATH (exact, arbitrary inputs): chunked smem recompute ----
    float* dst = reinterpret_cast<float*>(dst4);
#pragma unroll
    for (int k = 0; k < VPT; ++k) {
        v[k].x *= scale; v[k].y *= scale; v[k].z *= scale; v[k].w *= scale;
    }
    for (int c = 0; c < T_DIM / CHUNK; ++c) {
        const int k0 = 2 * c, k1 = 2 * c + 1, kh = (2 * c + 2) & (VPT - 1);
        // stage chunk c (elements [c*8192, (c+1)*8192)) + 12-elem halo.
        // element 4*(t + k*NT)+cc -> local index 4*t (k==k0), 4096+4*t (k==k1).
        float4* ys4 = reinterpret_cast<float4*>(ys);
        ys4[tid]      = v[k0];
        ys4[NT + tid] = v[k1];
        if (tid < 3) ys4[2 * NT + tid] = v[kh];      // halo wraps via & mask
        __syncthreads();

        float a[CPT + 10];
        const int st = CPT * tid;
#pragma unroll
        for (int j = 0; j < CPT + 10; ++j) a[j] = ys[st + j];
        // 4 damping iterations, forward in-place (valid range shrinks by d)
#pragma unroll
        for (int j = 0; j < CPT + 9; ++j) {
            const float t = a[j] + a[j + 1];
            a[j] *= fminf(__fdividef(2.0f, 1.0f + t), 1.0f);
        }
#pragma unroll
        for (int j = 0; j < CPT + 7; ++j) {
            const float t = a[j] + a[j + 2];
            a[j] *= fminf(__fdividef(2.0f, 1.0f + t), 1.0f);
        }
#pragma unroll
        for (int j = 0; j < CPT + 4; ++j) {
            const float t = a[j] + a[j + 3];
            a[j] *= fminf(__fdividef(2.0f, 1.0f + t), 1.0f);
        }
#pragma unroll
        for (int j = 0; j < CPT; ++j) {
            const float t = a[j] + a[j + 4];
            a[j] *= fminf(__fdividef(2.0f, 1.0f + t), 1.0f);
        }
        if (c == 0 && tid == 0) a[0] = 0.0f;         // y[:,0] = 0
#pragma unroll
        for (int j = 0; j < CPT; ++j) dst[c * CHUNK + st + j] = a[j];
        __syncthreads();                              // protect ys before next chunk
    }
}

extern "C" void kernel_launch(void* const* d_in, const int* in_sizes, int n_in,
                              void* d_out, int out_size)
{
    // metadata order: scores [B,T] fp32, log_temperature scalar fp32 (pick by size)
    const float* scores;
    const float* log_temp;
    int n_scores;
    if (in_sizes[0] > in_sizes[1]) {
        scores = (const float*)d_in[0]; log_temp = (const float*)d_in[1];
        n_scores = in_sizes[0];
    } else {
        scores = (const float*)d_in[1]; log_temp = (const float*)d_in[0];
        n_scores = in_sizes[1];
    }
    const int B = n_scores / T_DIM;               // 512
    fused_selector<<<B, NT>>>(scores, log_temp, (float*)d_out);
}

// round 10
// speedup vs baseline: 1.8448x; 1.0689x over previous
#include <cuda_runtime.h>
#include <cuda_bf16.h>

// DifferentiableSelector, persistent fused kernel (grid=128, 4 rows/CTA):
//  - row fully register-resident (8 x float4 / thread), scores read ONCE.
//  - cross-row software pipeline: after the budget reduction of row r, the
//    stores of row r and the loads of row r+128 are issued back-to-back, so
//    DRAM reads and writes overlap continuously (fixes R8's phase
//    serialization: load-all / barrier / store-all never overlapped).
//  - sigmoid = ex2.approx (1 MUFU) + FMA-pipe Newton reciprocal (seed + 3
//    steps on d in (1,2], rel err ~3e-9).
//  - identity-damping proof: 2*scale*ymax <= 1 => every damping factor
//    min(2/(1+a+b),1) == 1 exactly (damping only shrinks values) -> fast path
//    stores y*scale straight from registers. Exact chunked slow path kept.

static constexpr int   T_DIM = 32768;
static constexpr int   NT    = 1024;
static constexpr int   VPT   = T_DIM / NT / 4;   // 8 float4 per thread
static constexpr int   GRID  = 128;              // 512 rows / 128 = 4 rows/CTA
static constexpr float K_SEL = 64.0f;

// slow-path chunking: 4 chunks of 8192 elements, halo 10 (use 12 = 3 float4)
static constexpr int CHUNK = 8192;
static constexpr int CPT   = CHUNK / NT;         // 8 contiguous elems/thread

__device__ __forceinline__ float ex2_approx(float x) {
    float r; asm("ex2.approx.ftz.f32 %0, %1;" : "=f"(r) : "f"(x)); return r;
}

// sigmoid(x*invt) via 1 MUFU + Newton reciprocal; updates sum and max.
__device__ __forceinline__ float sig1(float x, float c2, float& sum, float& mx) {
    const float e = ex2_approx(-fabsf(x) * c2);     // e in (0, 1]
    const float d = 1.0f + e;                       // d in (1, 2]
    float r = fmaf(-0.5f, d, 1.45710678f);          // minimax seed, 8.6e-2
    float t = fmaf(d, r, -2.0f); r = -r * t;        // Newton 1: 7.4e-3
    t = fmaf(d, r, -2.0f); r = -r * t;              // Newton 2: 5.4e-5
    t = fmaf(d, r, -2.0f); r = -r * t;              // Newton 3: 2.9e-9
    const float s = (x >= 0.0f) ? r : e * r;
    sum += s;
    mx = fmaxf(mx, s);
    return s;
}

__global__ __launch_bounds__(NT, 1)
void fused_persistent(const float* __restrict__ scores,
                      const float* __restrict__ log_temp,
                      float* __restrict__ out, int B)
{
    __shared__ alignas(16) float ys[CHUNK + 12];   // slow path staging
    __shared__ float reds[32], redm[32];
    __shared__ float s_scale;
    __shared__ int   s_fast;

    const int tid = threadIdx.x;
    const float4* src4b = reinterpret_cast<const float4*>(scores);
    float4*       dst4b = reinterpret_cast<float4*>(out);

    float temp = __expf(log_temp[0]);
    temp = fminf(fmaxf(temp, 0.1f), 10.0f);
    const float c2 = __fdividef(1.442695040888963f, temp);   // log2(e)/temp

    int r = blockIdx.x;
    if (r >= B) return;

    // ---- prologue: load + sigmoid first row ----
    float4 v[VPT];
    {
        const float4* src4 = src4b + (size_t)r * (T_DIM / 4);
#pragma unroll
        for (int k = 0; k < VPT; ++k) v[k] = __ldcs(src4 + tid + k * NT);
    }
    float sum = 0.0f, mx = 0.0f;
#pragma unroll
    for (int k = 0; k < VPT; ++k) {
        v[k].x = sig1(v[k].x, c2, sum, mx);
        v[k].y = sig1(v[k].y, c2, sum, mx);
        v[k].z = sig1(v[k].z, c2, sum, mx);
        v[k].w = sig1(v[k].w, c2, sum, mx);
    }

    while (true) {
        // ---- block reduction: sum (budget) + max (identity proof) ----
#pragma unroll
        for (int o = 16; o > 0; o >>= 1) {
            sum += __shfl_xor_sync(0xffffffffu, sum, o);
            mx = fmaxf(mx, __shfl_xor_sync(0xffffffffu, mx, o));
        }
        if ((tid & 31) == 0) { reds[tid >> 5] = sum; redm[tid >> 5] = mx; }
        __syncthreads();
        if (tid < 32) {
            float s = reds[tid];
            float m = redm[tid];
#pragma unroll
            for (int o = 16; o > 0; o >>= 1) {
                s += __shfl_xor_sync(0xffffffffu, s, o);
                m = fmaxf(m, __shfl_xor_sync(0xffffffffu, m, o));
            }
            if (tid == 0) {
                const float b     = fmaxf(s, 1e-6f);
                const float scale = fminf(K_SEL / b, 1.0f);
                s_scale = scale;
                s_fast  = (2.0f * scale * m <= 1.0f) ? 1 : 0;
            }
        }
        __syncthreads();
        const float scale = s_scale;
        const int   fast  = s_fast;

        const int rn = r + GRID;
        const bool has_next = rn < B;
        float4*       dst4  = dst4b + (size_t)r * (T_DIM / 4);
        const float4* nsrc4 = src4b + (size_t)rn * (T_DIM / 4);

        if (fast) {
            // ---- FAST PATH: stores of row r, then loads of row r+GRID ----
#pragma unroll
            for (int k = 0; k < VPT; ++k) {
                v[k].x *= scale; v[k].y *= scale; v[k].z *= scale; v[k].w *= scale;
            }
            if (tid == 0) v[0].x = 0.0f;                 // y[:,0] = 0
#pragma unroll
            for (int k = 0; k < VPT; ++k) __stcs(dst4 + tid + k * NT, v[k]);
            if (has_next) {
#pragma unroll
                for (int k = 0; k < VPT; ++k) v[k] = __ldcs(nsrc4 + tid + k * NT);
            }
        } else {
            // ---- SLOW PATH (exact): chunked smem recompute of 4 damp iters ----
            float* dst = reinterpret_cast<float*>(dst4);
#pragma unroll
            for (int k = 0; k < VPT; ++k) {
                v[k].x *= scale; v[k].y *= scale; v[k].z *= scale; v[k].w *= scale;
            }
            for (int c = 0; c < T_DIM / CHUNK; ++c) {
                const int k0 = 2 * c, k1 = 2 * c + 1, kh = (2 * c + 2) & (VPT - 1);
                float4* ys4 = reinterpret_cast<float4*>(ys);
                ys4[tid]      = v[k0];
                ys4[NT + tid] = v[k1];
                if (tid < 3) ys4[2 * NT + tid] = v[kh];  // halo (wraps via mask)
                __syncthreads();

                float a[CPT + 10];
                const int st = CPT * tid;
#pragma unroll
                for (int j = 0; j < CPT + 10; ++j) a[j] = ys[st + j];
#pragma unroll
                for (int j = 0; j < CPT + 9; ++j) {      // d=1
                    const float t = a[j] + a[j + 1];
                    a[j] *= fminf(__fdividef(2.0f, 1.0f + t), 1.0f);
                }
#pragma unroll
                for (int j = 0; j < CPT + 7; ++j) {      // d=2
                    const float t = a[j] + a[j + 2];
                    a[j] *= fminf(__fdividef(2.0f, 1.0f + t), 1.0f);
                }
#pragma unroll
                for (int j = 0; j < CPT + 4; ++j) {      // d=3
                    const float t = a[j] + a[j + 3];
                    a[j] *= fminf(__fdividef(2.0f, 1.0f + t), 1.0f);
                }
#pragma unroll
                for (int j = 0; j < CPT; ++j) {          // d=4
                    const float t = a[j] + a[j + 4];
                    a[j] *= fminf(__fdividef(2.0f, 1.0f + t), 1.0f);
                }
                if (c == 0 && tid == 0) a[0] = 0.0f;     // y[:,0] = 0
#pragma unroll
                for (int j = 0; j < CPT; ++j) dst[c * CHUNK + st + j] = a[j];
                __syncthreads();
            }
            if (has_next) {
#pragma unroll
                for (int k = 0; k < VPT; ++k) v[k] = __ldcs(nsrc4 + tid + k * NT);
            }
        }

        if (!has_next) break;

        // ---- sigmoid + partial sums for the prefetched row ----
        sum = 0.0f; mx = 0.0f;
#pragma unroll
        for (int k = 0; k < VPT; ++k) {
            v[k].x = sig1(v[k].x, c2, sum, mx);
            v[k].y = sig1(v[k].y, c2, sum, mx);
            v[k].z = sig1(v[k].z, c2, sum, mx);
            v[k].w = sig1(v[k].w, c2, sum, mx);
        }
        r = rn;
    }
}

extern "C" void kernel_launch(void* const* d_in, const int* in_sizes, int n_in,
                              void* d_out, int out_size)
{
    // metadata order: scores [B,T] fp32, log_temperature scalar fp32 (pick by size)
    const float* scores;
    const float* log_temp;
    int n_scores;
    if (in_sizes[0] > in_sizes[1]) {
        scores = (const float*)d_in[0]; log_temp = (const float*)d_in[1];
        n_scores = in_sizes[0];
    } else {
        scores = (const float*)d_in[1]; log_temp = (const float*)d_in[0];
        n_scores = in_sizes[1];
    }
    const int B = n_scores / T_DIM;               // 512
    const int grid = (B < GRID) ? B : GRID;
    fused_persistent<<<grid, NT>>>(scores, log_temp, (float*)d_out, B);
}

// round 11
// speedup vs baseline: 1.9704x; 1.0681x over previous
#include <cuda_runtime.h>
#include <cuda_bf16.h>
#include <cstdint>

// DifferentiableSelector, persistent + TMA double-buffered fused kernel.
//  grid=128 CTAs, 4 rows each. Row r+1 is fetched by cp.async.bulk (TMA) into
//  a 128 KB smem buffer while row r is sigmoid'ed (LDS reads), reduced, and
//  stored — DRAM reads and writes overlap continuously and the read latency
//  is hidden behind a whole row of work instead of 32 warps' MLP.
//  sigmoid = ex2.approx (1 MUFU) + FMA-pipe Newton reciprocal (~3e-9).
//  Identity-damping proof: 2*scale*ymax <= 1 => every factor
//  min(2/(1+a+b),1) == 1 exactly -> fast path stores y*scale from registers.
//  Exact chunked slow path retained (uses separate ys staging region).

static constexpr int   T_DIM = 32768;
static constexpr int   NT    = 1024;
static constexpr int   VPT   = T_DIM / NT / 4;   // 8 float4 per thread
static constexpr int   GRID  = 128;              // 512 rows / 128 = 4 rows/CTA
static constexpr float K_SEL = 64.0f;
static constexpr int   BUF_BYTES = T_DIM * 4;    // 128 KB row buffer

// slow-path chunking: 4 chunks of 8192 elements, halo 10 (use 12 = 3 float4)
static constexpr int CHUNK = 8192;
static constexpr int CPT   = CHUNK / NT;         // 8 contiguous elems/thread
static constexpr int DYN_SMEM = BUF_BYTES + (CHUNK + 12) * 4;   // 163888 B

__device__ __forceinline__ float ex2_approx(float x) {
    float r; asm("ex2.approx.ftz.f32 %0, %1;" : "=f"(r) : "f"(x)); return r;
}
__device__ __forceinline__ uint32_t smem_u32(const void* p) {
    uint32_t a;
    asm("{ .reg .u64 t; cvta.to.shared.u64 t, %1; cvt.u32.u64 %0, t; }"
        : "=r"(a) : "l"(p));
    return a;
}
__device__ __forceinline__ void mbar_init(uint32_t mbar, uint32_t cnt) {
    asm volatile("mbarrier.init.shared.b64 [%0], %1;" :: "r"(mbar), "r"(cnt) : "memory");
}
__device__ __forceinline__ void mbar_expect_tx(uint32_t mbar, uint32_t bytes) {
    asm volatile("mbarrier.arrive.expect_tx.shared.b64 _, [%0], %1;"
                 :: "r"(mbar), "r"(bytes) : "memory");
}
__device__ __forceinline__ void bulk_ld(uint32_t dst_smem, const void* src,
                                        uint32_t bytes, uint32_t mbar) {
    asm volatile(
        "cp.async.bulk.shared::cta.global.mbarrier::complete_tx::bytes [%0], [%1], %2, [%3];"
        :: "r"(dst_smem), "l"(src), "r"(bytes), "r"(mbar) : "memory");
}
__device__ __forceinline__ void mbar_wait(uint32_t mbar, uint32_t parity) {
    asm volatile(
        "{\n\t"
        ".reg .pred P;\n\t"
        "WAIT_%=:\n\t"
        "mbarrier.try_wait.parity.acquire.cta.shared::cta.b64 P, [%0], %1, 0x989680;\n\t"
        "@P bra.uni DONE_%=;\n\t"
        "bra.uni WAIT_%=;\n\t"
        "DONE_%=:\n\t"
        "}" :: "r"(mbar), "r"(parity) : "memory");
}

// sigmoid(x*invt) via 1 MUFU + Newton reciprocal; updates sum and max.
__device__ __forceinline__ float sig1(float x, float c2, float& sum, float& mx) {
    const float e = ex2_approx(-fabsf(x) * c2);     // e in (0, 1]
    const float d = 1.0f + e;                       // d in (1, 2]
    float r = fmaf(-0.5f, d, 1.45710678f);          // minimax seed, 8.6e-2
    float t = fmaf(d, r, -2.0f); r = -r * t;        // Newton 1: 7.4e-3
    t = fmaf(d, r, -2.0f); r = -r * t;              // Newton 2: 5.4e-5
    t = fmaf(d, r, -2.0f); r = -r * t;              // Newton 3: 2.9e-9
    const float s = (x >= 0.0f) ? r : e * r;
    sum += s;
    mx = fmaxf(mx, s);
    return s;
}

__global__ __launch_bounds__(NT, 1)
void fused_tma(const float* __restrict__ scores,
               const float* __restrict__ log_temp,
               float* __restrict__ out, int B)
{
    extern __shared__ __align__(16) float dsm[];
    float4* buf4 = reinterpret_cast<float4*>(dsm);          // 128 KB row buffer
    float*  ys   = dsm + T_DIM;                             // slow-path staging
    __shared__ float reds[32], redm[32];
    __shared__ float s_scale;
    __shared__ int   s_fast;
    __shared__ __align__(8) uint64_t mbar_storage;

    const int tid = threadIdx.x;
    const uint32_t mbar = smem_u32(&mbar_storage);
    const uint32_t bufa = smem_u32(dsm);

    float temp = __expf(log_temp[0]);
    temp = fminf(fmaxf(temp, 0.1f), 10.0f);
    const float c2 = __fdividef(1.442695040888963f, temp);   // log2(e)/temp

    int r = blockIdx.x;                 // grid <= B guaranteed by launcher
    if (tid == 0) mbar_init(mbar, 1);
    __syncthreads();
    if (tid == 0) {
        mbar_expect_tx(mbar, BUF_BYTES);
        bulk_ld(bufa, scores + (size_t)r * T_DIM, BUF_BYTES, mbar);
    }
    uint32_t parity = 0;

    while (true) {
        // ---- wait for TMA of row r, sigmoid from smem into registers ----
        mbar_wait(mbar, parity);
        float4 v[VPT];
#pragma unroll
        for (int k = 0; k < VPT; ++k) v[k] = buf4[tid + k * NT];
        float sum = 0.0f, mx = 0.0f;
#pragma unroll
        for (int k = 0; k < VPT; ++k) {
            v[k].x = sig1(v[k].x, c2, sum, mx);
            v[k].y = sig1(v[k].y, c2, sum, mx);
            v[k].z = sig1(v[k].z, c2, sum, mx);
            v[k].w = sig1(v[k].w, c2, sum, mx);
        }

        // ---- reduction; TMA for row r+GRID issued inside the first barrier ----
#pragma unroll
        for (int o = 16; o > 0; o >>= 1) {
            sum += __shfl_xor_sync(0xffffffffu, sum, o);
            mx = fmaxf(mx, __shfl_xor_sync(0xffffffffu, mx, o));
        }
        if ((tid & 31) == 0) { reds[tid >> 5] = sum; redm[tid >> 5] = mx; }
        __syncthreads();                 // all warps done reading buf4
        const int  rn = r + GRID;
        const bool has_next = rn < B;
        if (tid == 0 && has_next) {      // refill buffer while we reduce/store
            mbar_expect_tx(mbar, BUF_BYTES);
            bulk_ld(bufa, scores + (size_t)rn * T_DIM, BUF_BYTES, mbar);
        }
        if (tid < 32) {
            float s = reds[tid];
            float m = redm[tid];
#pragma unroll
            for (int o = 16; o > 0; o >>= 1) {
                s += __shfl_xor_sync(0xffffffffu, s, o);
                m = fmaxf(m, __shfl_xor_sync(0xffffffffu, m, o));
            }
            if (tid == 0) {
                const float b     = fmaxf(s, 1e-6f);
                const float scale = fminf(K_SEL / b, 1.0f);
                s_scale = scale;
                s_fast  = (2.0f * scale * m <= 1.0f) ? 1 : 0;
            }
        }
        __syncthreads();
        const float scale = s_scale;
        float4* dst4 = reinterpret_cast<float4*>(out) + (size_t)r * (T_DIM / 4);

#pragma unroll
        for (int k = 0; k < VPT; ++k) {
            v[k].x *= scale; v[k].y *= scale; v[k].z *= scale; v[k].w *= scale;
        }

        if (s_fast) {
            // ---- FAST PATH: damping is the identity -> store from registers ----
            if (tid == 0) v[0].x = 0.0f;                 // y[:,0] = 0
#pragma unroll
            for (int k = 0; k < VPT; ++k) __stcs(dst4 + tid + k * NT, v[k]);
        } else {
            // ---- SLOW PATH (exact): chunked recompute in separate ys region ----
            float* dst = reinterpret_cast<float*>(dst4);
            for (int c = 0; c < T_DIM / CHUNK; ++c) {
                const int k0 = 2 * c, k1 = 2 * c + 1, kh = (2 * c + 2) & (VPT - 1);
                float4* ys4 = reinterpret_cast<float4*>(ys);
                ys4[tid]      = v[k0];
                ys4[NT + tid] = v[k1];
                if (tid < 3) ys4[2 * NT + tid] = v[kh];  // halo (wraps via mask)
                __syncthreads();

                float a[CPT + 10];
                const int st = CPT * tid;
#pragma unroll
                for (int j = 0; j < CPT + 10; ++j) a[j] = ys[st + j];
#pragma unroll
                for (int j = 0; j < CPT + 9; ++j) {      // d=1
                    const float t = a[j] + a[j + 1];
                    a[j] *= fminf(__fdividef(2.0f, 1.0f + t), 1.0f);
                }
#pragma unroll
                for (int j = 0; j < CPT + 7; ++j) {      // d=2
                    const float t = a[j] + a[j + 2];
                    a[j] *= fminf(__fdividef(2.0f, 1.0f + t), 1.0f);
                }
#pragma unroll
                for (int j = 0; j < CPT + 4; ++j) {      // d=3
                    const float t = a[j] + a[j + 3];
                    a[j] *= fminf(__fdividef(2.0f, 1.0f + t), 1.0f);
                }
#pragma unroll
                for (int j = 0; j < CPT; ++j) {          // d=4
                    const float t = a[j] + a[j + 4];
                    a[j] *= fminf(__fdividef(2.0f, 1.0f + t), 1.0f);
                }
                if (c == 0 && tid == 0) a[0] = 0.0f;     // y[:,0] = 0
#pragma unroll
                for (int j = 0; j < CPT; ++j) dst[c * CHUNK + st + j] = a[j];
                __syncthreads();
            }
        }

        if (!has_next) break;
        r = rn;
        parity ^= 1u;
    }
}

extern "C" void kernel_launch(void* const* d_in, const int* in_sizes, int n_in,
                              void* d_out, int out_size)
{
    // metadata order: scores [B,T] fp32, log_temperature scalar fp32 (pick by size)
    const float* scores;
    const float* log_temp;
    int n_scores;
    if (in_sizes[0] > in_sizes[1]) {
        scores = (const float*)d_in[0]; log_temp = (const float*)d_in[1];
        n_scores = in_sizes[0];
    } else {
        scores = (const float*)d_in[1]; log_temp = (const float*)d_in[0];
        n_scores = in_sizes[1];
    }
    const int B = n_scores / T_DIM;               // 512
    const int grid = (B < GRID) ? B : GRID;

    cudaFuncSetAttribute(fused_tma,
                         cudaFuncAttributeMaxDynamicSharedMemorySize, DYN_SMEM);
    fused_tma<<<grid, NT, DYN_SMEM>>>(scores, log_temp, (float*)d_out, B);
}